// round 7
// baseline (speedup 1.0000x reference)
#include <cuda_runtime.h>

#define SEQ   8192
#define HD    1024
#define G4    4096
#define NIN   64
#define NLAYER 5
#define NCTA  128

// dynamic SMEM: 32768 floats Wih slice (128KB) + 2*1024 floats h buffers (8KB)
#define SMEM_BYTES (131072 + 8192)

// ---------------- scratch (device globals; no allocation allowed) ------------
__device__ float    g_bufA[(size_t)SEQ * HD];   // X0: first-layer output
__device__ float    g_bufB[(size_t)SEQ * HD];   // X4: last-layer output
__device__ float    g_Z0[(size_t)SEQ * G4];     // input-projection ping
__device__ float    g_Z1[(size_t)SEQ * G4];     // input-projection pong
__device__ float    g_h[2 * HD];                // double-buffered hidden state
__device__ unsigned g_flags[NCTA];              // per-CTA monotonic step flags

// ---------------- math helpers ----------------------------------------------
__device__ __forceinline__ float sigmf(float x) { return 1.0f / (1.0f + __expf(-x)); }
__device__ __forceinline__ float tanh_fast(float x) { return 1.0f - 2.0f / (__expf(2.0f * x) + 1.0f); }

__device__ __forceinline__ unsigned ld_acq(const unsigned* p) {
    unsigned v;
    asm volatile("ld.acquire.gpu.global.b32 %0, [%1];" : "=r"(v) : "l"(p) : "memory");
    return v;
}
__device__ __forceinline__ void st_rel(unsigned* p, unsigned v) {
    asm volatile("st.release.gpu.global.b32 [%0], %1;" :: "l"(p), "r"(v) : "memory");
}
__device__ __forceinline__ void st_rlx_f(float* p, float v) {
    asm volatile("st.relaxed.gpu.global.b32 [%0], %1;" :: "l"(p), "f"(v) : "memory");
}
__device__ __forceinline__ unsigned long long lds64(unsigned a) {
    unsigned long long v;
    asm volatile("ld.shared.b64 %0, [%1];" : "=l"(v) : "r"(a));
    return v;
}

// ---------------- init: flags = 0, seed layer-0 h_{-1} -----------------------
__global__ void k_init(const float* __restrict__ h0l) {
    const int i = threadIdx.x + blockIdx.x * blockDim.x;   // 0..1023
    if (i < NCTA) g_flags[i] = 0u;
    g_h[HD + i] = h0l[i];    // t=0 reads buf[1]
}

// ---------------- prep (layers >= 1): seed h_{-1} = h0[layer] ----------------
__global__ void k_prep(const float* __restrict__ h0l) {
    const int i = threadIdx.x + blockIdx.x * blockDim.x;
    if (i < HD) g_h[HD + i] = h0l[i];
}

// ---------------- first layer: leaky_relu(x @ w1^T + b1) ---------------------
__global__ __launch_bounds__(256) void k_first(const float* __restrict__ x,
                                               const float* __restrict__ w1,
                                               const float* __restrict__ b1,
                                               float* __restrict__ out) {
    __shared__ float xs[64][NIN];
    __shared__ float ws[64][NIN + 1];
    const int t0 = blockIdx.x * 64;
    const int h0 = blockIdx.y * 64;
    const int tid = threadIdx.x;

    for (int i = tid; i < 64 * NIN; i += 256)
        xs[i >> 6][i & 63] = x[(size_t)(t0 + (i >> 6)) * NIN + (i & 63)];
    for (int i = tid; i < 64 * NIN; i += 256)
        ws[i >> 6][i & 63] = w1[(size_t)(h0 + (i >> 6)) * NIN + (i & 63)];
    __syncthreads();

    const int h = tid & 63, tq = tid >> 6;
    float acc[16];
#pragma unroll
    for (int i = 0; i < 16; i++) acc[i] = 0.0f;

#pragma unroll 16
    for (int k = 0; k < NIN; k++) {
        const float wv = ws[h][k];
#pragma unroll
        for (int i = 0; i < 16; i++) acc[i] = fmaf(xs[tq * 16 + i][k], wv, acc[i]);
    }
    const float bb = b1[h0 + h];
#pragma unroll
    for (int i = 0; i < 16; i++) {
        float v = acc[i] + bb;
        v = (v >= 0.0f) ? v : 0.01f * v;
        out[(size_t)(t0 + tq * 16 + i) * HD + h0 + h] = v;
    }
}

// ---------------- layer-0 input GEMM: Z0 = X0 @ Wih0^T (NO bias) -------------
__global__ __launch_bounds__(256, 2) void k_gemm(const float* __restrict__ A,   // (SEQ, HD)
                                                 const float* __restrict__ W,   // (G4, HD)
                                                 float* __restrict__ Z) {
    __shared__ float As[8][128];
    __shared__ float Bs[8][128];
    const int tid = threadIdx.x;
    const int tx = tid & 15, ty = tid >> 4;
    const int m0 = blockIdx.y * 128, n0 = blockIdx.x * 128;
    const int lr = tid >> 1, lk = (tid & 1) * 4;

    const float* Ap = A + (size_t)(m0 + lr) * HD + lk;
    const float* Wp = W + (size_t)(n0 + lr) * HD + lk;

    float acc[8][8];
#pragma unroll
    for (int i = 0; i < 8; i++)
#pragma unroll
        for (int j = 0; j < 8; j++) acc[i][j] = 0.0f;

    float4 av = *(const float4*)(Ap);
    float4 bv = *(const float4*)(Wp);

    for (int k0 = 0; k0 < HD; k0 += 8) {
        __syncthreads();
        As[lk + 0][lr] = av.x; As[lk + 1][lr] = av.y; As[lk + 2][lr] = av.z; As[lk + 3][lr] = av.w;
        Bs[lk + 0][lr] = bv.x; Bs[lk + 1][lr] = bv.y; Bs[lk + 2][lr] = bv.z; Bs[lk + 3][lr] = bv.w;
        __syncthreads();
        if (k0 + 8 < HD) {
            av = *(const float4*)(Ap + k0 + 8);
            bv = *(const float4*)(Wp + k0 + 8);
        }
#pragma unroll
        for (int kk = 0; kk < 8; kk++) {
            float ar[8], br[8];
            *(float4*)(ar)     = *(const float4*)&As[kk][ty * 8];
            *(float4*)(ar + 4) = *(const float4*)&As[kk][ty * 8 + 4];
            *(float4*)(br)     = *(const float4*)&Bs[kk][tx * 8];
            *(float4*)(br + 4) = *(const float4*)&Bs[kk][tx * 8 + 4];
#pragma unroll
            for (int i = 0; i < 8; i++)
#pragma unroll
                for (int j = 0; j < 8; j++) acc[i][j] = fmaf(ar[i], br[j], acc[i][j]);
        }
    }
#pragma unroll
    for (int i = 0; i < 8; i++) {
        const size_t m = (size_t)(m0 + ty * 8 + i);
        float4 o0, o1;
        o0.x = acc[i][0]; o0.y = acc[i][1]; o0.z = acc[i][2]; o0.w = acc[i][3];
        o1.x = acc[i][4]; o1.y = acc[i][5]; o1.z = acc[i][6]; o1.w = acc[i][7];
        *(float4*)&Z[m * G4 + n0 + tx * 8]     = o0;
        *(float4*)&Z[m * G4 + n0 + tx * 8 + 4] = o1;
    }
}

// ---------------- recurrent persistent kernel, fused next-layer GEMM ---------
// 128 CTAs x 256 threads. CTA b owns units [8b,8b+8); warp w -> unit u = 8b+w.
// Whh rows in registers (f32x2 pairs). If fuse: Wih_{l+1} slice (its own 32 rows)
// resident in SMEM; during each step's sync-wait window the CTA computes
// z_{l+1}[t-2] = Wih_{l+1,rows} @ h_{t-2} from the old SMEM h buffer (race-free:
// reads are pre-barrier, next overwrite is post-barrier). z excludes bias; bias
// is added at consumption (lane<4 holds b_ih+b_hh for its gate).
__global__ __launch_bounds__(256, 1) void k_rec(const float* __restrict__ Whh,  // (G4, HD)
                                                const float* __restrict__ Wn,   // Wih_{l+1}
                                                const float* __restrict__ c0l,  // (HD)
                                                const float* __restrict__ bih,
                                                const float* __restrict__ bhh,
                                                const float* __restrict__ Zin,  // (SEQ, G4)
                                                float* __restrict__ Zout,       // (SEQ, G4)
                                                float* __restrict__ Xout,       // (SEQ, HD)
                                                unsigned base, int fuse) {
    extern __shared__ float smem[];             // [0,32768): Wih slice, [32768,+2048): sh
    const int tid = threadIdx.x;
    const int w = tid >> 5, lane = tid & 31;
    const int u = blockIdx.x * 8 + w;

    unsigned S;
    asm("{ .reg .u64 t; cvta.to.shared.u64 t, %1; cvt.u32.u64 %0, t; }"
        : "=r"(S) : "l"((void*)smem));

    // preload this CTA's Wih_{l+1} slice (32 rows x 1024) into SMEM, warp-local
    if (fuse) {
#pragma unroll
        for (int g = 0; g < 4; g++) {
            const float* src = Wn + (size_t)(g * HD + u) * HD;
            float* dst = smem + ((w * 4 + g) << 10);
            for (int k = lane * 4; k < HD; k += 128)
                *(float4*)(dst + k) = *(const float4*)(src + k);
        }
    }

    // Whh weight pairs in registers: lane owns k in {64j+2*lane, 64j+2*lane+1}
    unsigned long long wp[4][16];
#pragma unroll
    for (int g = 0; g < 4; g++) {
        const float* rp = Whh + (size_t)(g * HD + u) * HD + 2 * lane;
#pragma unroll
        for (int j = 0; j < 16; j++) {
            const float2 v = *(const float2*)(rp + 64 * j);
            asm("mov.b64 %0, {%1, %2};" : "=l"(wp[g][j]) : "f"(v.x), "f"(v.y));
        }
    }
    float zb = 0.0f;
    if (lane < 4) zb = bih[lane * HD + u] + bhh[lane * HD + u];
    float c = c0l[u];   // only lane 0's copy is used

    const unsigned shb = S + 131072u + (unsigned)lane * 8u;   // h-buffer base for LDS
    const unsigned wb0 = S + ((unsigned)(w * 4) << 12) + (unsigned)lane * 8u;
    const int tend = fuse ? (SEQ + 1) : (SEQ - 1);

#pragma unroll 1
    for (int t = 0; t <= tend; t++) {
        const unsigned target = base + (unsigned)t;
        const unsigned* fp = &g_flags[tid >> 1];

        // z prefetch for this step's gates (lane g < 4)
        float z = 0.f;
        if (t < SEQ && lane < 4)
            z = __ldcg(Zin + (size_t)t * G4 + (size_t)lane * HD + u);

        // ---- phase A: fused gemm on h_{t-2} (old sh buffer), poll-interleaved
        unsigned long long za0 = 0ull, za1 = 0ull, za2 = 0ull, za3 = 0ull;
        bool ready = false;
        if (fuse && t >= 2) {
            const unsigned hold = shb + (((unsigned)(t - 1) & 1u) << 12);
#pragma unroll
            for (int c4 = 0; c4 < 4; c4++) {
#pragma unroll
                for (int jj = 0; jj < 4; jj++) {
                    const int j = c4 * 4 + jj;
                    const unsigned long long hp = lds64(hold + (unsigned)(j * 256));
                    const unsigned long long w0 = lds64(wb0 + (unsigned)(j * 256));
                    const unsigned long long w1 = lds64(wb0 + 4096u + (unsigned)(j * 256));
                    const unsigned long long w2 = lds64(wb0 + 8192u + (unsigned)(j * 256));
                    const unsigned long long w3 = lds64(wb0 + 12288u + (unsigned)(j * 256));
                    asm("fma.rn.f32x2 %0, %1, %2, %0;" : "+l"(za0) : "l"(w0), "l"(hp));
                    asm("fma.rn.f32x2 %0, %1, %2, %0;" : "+l"(za1) : "l"(w1), "l"(hp));
                    asm("fma.rn.f32x2 %0, %1, %2, %0;" : "+l"(za2) : "l"(w2), "l"(hp));
                    asm("fma.rn.f32x2 %0, %1, %2, %0;" : "+l"(za3) : "l"(w3), "l"(hp));
                }
                if (t <= SEQ && !ready) ready = (ld_acq(fp) >= target);
            }
        }

        // ---- phase B: wait for slice producer, stage h_{t-1} into SMEM
        if (t <= SEQ) {
            if (!ready) { while (ld_acq(fp) < target) {} }
            const float4 v = __ldcg((const float4*)(g_h + ((t + 1) & 1) * HD) + tid);
            *(float4*)&smem[32768 + (t & 1) * 1024 + tid * 4] = v;
            __syncthreads();
        }

        // ---- phase C: recurrent dot + gates + publish
        if (t < SEQ) {
            const unsigned sbase = shb + ((unsigned)(t & 1) << 12);
            unsigned long long a0 = 0ull, a1 = 0ull, a2 = 0ull, a3 = 0ull;
#pragma unroll
            for (int j = 0; j < 16; j++) {
                const unsigned long long hp = lds64(sbase + (unsigned)(j * 256));
                asm("fma.rn.f32x2 %0, %1, %2, %0;" : "+l"(a0) : "l"(wp[0][j]), "l"(hp));
                asm("fma.rn.f32x2 %0, %1, %2, %0;" : "+l"(a1) : "l"(wp[1][j]), "l"(hp));
                asm("fma.rn.f32x2 %0, %1, %2, %0;" : "+l"(a2) : "l"(wp[2][j]), "l"(hp));
                asm("fma.rn.f32x2 %0, %1, %2, %0;" : "+l"(a3) : "l"(wp[3][j]), "l"(hp));
            }
            float s0, s1, s2, s3;
            {
                float x, y;
                asm("mov.b64 {%0,%1}, %2;" : "=f"(x), "=f"(y) : "l"(a0)); s0 = x + y;
                asm("mov.b64 {%0,%1}, %2;" : "=f"(x), "=f"(y) : "l"(a1)); s1 = x + y;
                asm("mov.b64 {%0,%1}, %2;" : "=f"(x), "=f"(y) : "l"(a2)); s2 = x + y;
                asm("mov.b64 {%0,%1}, %2;" : "=f"(x), "=f"(y) : "l"(a3)); s3 = x + y;
            }
#pragma unroll
            for (int off = 16; off; off >>= 1) {
                s0 += __shfl_xor_sync(0xffffffffu, s0, off);
                s1 += __shfl_xor_sync(0xffffffffu, s1, off);
                s2 += __shfl_xor_sync(0xffffffffu, s2, off);
                s3 += __shfl_xor_sync(0xffffffffu, s3, off);
            }
            const float sg  = (lane == 0) ? s0 : (lane == 1) ? s1 : (lane == 2) ? s2 : s3;
            const float act = (lane == 2) ? tanh_fast(sg + z + zb) : sigmf(sg + z + zb);
            const float ig = __shfl_sync(0xffffffffu, act, 0);
            const float fg = __shfl_sync(0xffffffffu, act, 1);
            const float gg = __shfl_sync(0xffffffffu, act, 2);
            const float og = __shfl_sync(0xffffffffu, act, 3);
            if (lane == 0) {
                c = fg * c + ig * gg;
                const float h = og * tanh_fast(c);
                st_rlx_f(&g_h[(t & 1) * HD + u], h);
                if (!fuse) Xout[(size_t)t * HD + u] = h;   // last layer only
            }
            __syncthreads();
            if (tid == 0)
                st_rel(&g_flags[blockIdx.x], target + 1u);
        }

        // ---- phase D: reduce + store z_{l+1}[t-2] (off critical path)
        if (fuse && t >= 2) {
            float q0, q1, q2, q3;
            {
                float x, y;
                asm("mov.b64 {%0,%1}, %2;" : "=f"(x), "=f"(y) : "l"(za0)); q0 = x + y;
                asm("mov.b64 {%0,%1}, %2;" : "=f"(x), "=f"(y) : "l"(za1)); q1 = x + y;
                asm("mov.b64 {%0,%1}, %2;" : "=f"(x), "=f"(y) : "l"(za2)); q2 = x + y;
                asm("mov.b64 {%0,%1}, %2;" : "=f"(x), "=f"(y) : "l"(za3)); q3 = x + y;
            }
#pragma unroll
            for (int off = 16; off; off >>= 1) {
                q0 += __shfl_xor_sync(0xffffffffu, q0, off);
                q1 += __shfl_xor_sync(0xffffffffu, q1, off);
                q2 += __shfl_xor_sync(0xffffffffu, q2, off);
                q3 += __shfl_xor_sync(0xffffffffu, q3, off);
            }
            if (lane < 4) {
                const float zs = (lane == 0) ? q0 : (lane == 1) ? q1 : (lane == 2) ? q2 : q3;
                Zout[(size_t)(t - 2) * G4 + (size_t)lane * HD + u] = zs;
            }
        }
    }
}

// ---------------- final: tanh(leaky_relu(X) @ w2^T + b2) ---------------------
__global__ __launch_bounds__(256) void k_final(const float* __restrict__ Xin,
                                               const float* __restrict__ w2,   // (NIN, HD)
                                               const float* __restrict__ b2,
                                               float* __restrict__ y) {
    __shared__ float xs[64][65];
    __shared__ float ws[64][65];
    const int t0 = blockIdx.x * 64;
    const int tid = threadIdx.x;
    const int o = tid & 63, tq = tid >> 6;

    float acc[16];
#pragma unroll
    for (int i = 0; i < 16; i++) acc[i] = 0.0f;

    for (int k0 = 0; k0 < HD; k0 += 64) {
        __syncthreads();
        for (int i = tid; i < 64 * 64; i += 256) {
            const int r = i >> 6, cc = i & 63;
            float v = Xin[(size_t)(t0 + r) * HD + k0 + cc];
            xs[r][cc] = (v >= 0.0f) ? v : 0.01f * v;
            ws[r][cc] = w2[(size_t)r * HD + k0 + cc];
        }
        __syncthreads();
#pragma unroll 16
        for (int k = 0; k < 64; k++) {
            const float wv = ws[o][k];
#pragma unroll
            for (int i = 0; i < 16; i++) acc[i] = fmaf(xs[tq * 16 + i][k], wv, acc[i]);
        }
    }
    const float bb = b2[o];
#pragma unroll
    for (int i = 0; i < 16; i++)
        y[(size_t)(t0 + tq * 16 + i) * NIN + o] = tanh_fast(acc[i] + bb);
}

// ---------------- host launcher ----------------------------------------------
extern "C" void kernel_launch(void* const* d_in, const int* in_sizes, int n_in,
                              void* d_out, int out_size) {
    const float* data_in = (const float*)d_in[0];
    const float* w1      = (const float*)d_in[1];
    const float* b1      = (const float*)d_in[2];
    const float* W_ih    = (const float*)d_in[3];
    const float* W_hh    = (const float*)d_in[4];
    const float* b_ih    = (const float*)d_in[5];
    const float* b_hh    = (const float*)d_in[6];
    const float* w2      = (const float*)d_in[7];
    const float* b2      = (const float*)d_in[8];
    const float* h0      = (const float*)d_in[9];
    const float* c0      = (const float*)d_in[10];
    float* out = (float*)d_out;

    static float* dA = nullptr;
    static float* dB = nullptr;
    static float* dZ0 = nullptr;
    static float* dZ1 = nullptr;
    if (!dA) {   // host-side symbol queries + attribute set; not allocations
        cudaGetSymbolAddress((void**)&dA, g_bufA);
        cudaGetSymbolAddress((void**)&dB, g_bufB);
        cudaGetSymbolAddress((void**)&dZ0, g_Z0);
        cudaGetSymbolAddress((void**)&dZ1, g_Z1);
        cudaFuncSetAttribute(k_rec, cudaFuncAttributeMaxDynamicSharedMemorySize, SMEM_BYTES);
    }
    float* zb[2] = { dZ0, dZ1 };

    k_init<<<4, 256>>>(h0);                                          // 1
    k_first<<<dim3(SEQ / 64, HD / 64), 256>>>(data_in, w1, b1, dA);  // 2
    k_gemm<<<dim3(G4 / 128, SEQ / 128), 256>>>(dA, W_ih, dZ0);       // 3: layer-0 Z, biasless

    for (int l = 0; l < NLAYER; l++) {
        const int fuse = (l < NLAYER - 1) ? 1 : 0;
        if (l > 0)
            k_prep<<<4, 256>>>(h0 + (size_t)l * HD);
        k_rec<<<NCTA, 256, SMEM_BYTES>>>(W_hh + (size_t)l * G4 * HD,   // 4 for l=0 (profiled)
                                         W_ih + (size_t)(l + 1 < NLAYER ? l + 1 : l) * G4 * HD,
                                         c0 + (size_t)l * HD,
                                         b_ih + (size_t)l * G4,
                                         b_hh + (size_t)l * G4,
                                         zb[l & 1], zb[(l + 1) & 1],
                                         dB,
                                         (unsigned)(l * SEQ), fuse);
    }
    k_final<<<SEQ / 64, 256>>>(dB, w2, b2, out);
}

// round 9
// speedup vs baseline: 1.3509x; 1.3509x over previous
#include <cuda_runtime.h>

#define SEQ   8192
#define HD    1024
#define G4    4096
#define NIN   64
#define NLAYER 5
#define NCTA  128

#define CH_CTAS   148
#define GRID_REC  (NCTA + CH_CTAS)            // 276: 128 rec + 148 chase
#define CH_TILES  ((SEQ / 128) * (G4 / 128))  // 2048 tiles of 128x128

// ---------------- scratch (device globals; no allocation allowed) ------------
__device__ float    g_bufA[(size_t)SEQ * HD];   // activation ping
__device__ float    g_bufB[(size_t)SEQ * HD];   // activation pong
__device__ float    g_Z0[(size_t)SEQ * G4];     // input-projection ping
__device__ float    g_Z1[(size_t)SEQ * G4];     // input-projection pong
__device__ float    g_h[2 * HD];                // double-buffered hidden state
__device__ unsigned g_flags[NCTA];              // per-CTA monotonic step flags
__device__ int      g_tilectr[NLAYER];          // chase dynamic tile counters

// ---------------- math helpers ----------------------------------------------
__device__ __forceinline__ float sigmf(float x) { return 1.0f / (1.0f + __expf(-x)); }
__device__ __forceinline__ float tanh_fast(float x) { return 1.0f - 2.0f / (__expf(2.0f * x) + 1.0f); }

__device__ __forceinline__ unsigned ld_acq(const unsigned* p) {
    unsigned v;
    asm volatile("ld.acquire.gpu.global.b32 %0, [%1];" : "=r"(v) : "l"(p) : "memory");
    return v;
}
__device__ __forceinline__ void st_relx(unsigned* p, unsigned v) {
    asm volatile("st.relaxed.gpu.global.b32 [%0], %1;" :: "l"(p), "r"(v) : "memory");
}

// ---------------- init: flags/counters = 0, seed layer-0 h_{-1} --------------
__global__ void k_init(const float* __restrict__ h0l) {
    const int i = threadIdx.x + blockIdx.x * blockDim.x;   // 0..1023
    if (i < NCTA) g_flags[i] = 0u;
    if (i < NLAYER) g_tilectr[i] = 0;
    g_h[HD + i] = h0l[i];    // t=0 reads buf[1]
}

// ---------------- prep (layers >= 1): seed h_{-1} = h0[layer] ----------------
__global__ void k_prep(const float* __restrict__ h0l) {
    const int i = threadIdx.x + blockIdx.x * blockDim.x;
    if (i < HD) g_h[HD + i] = h0l[i];
}

// ---------------- first layer: leaky_relu(x @ w1^T + b1) ---------------------
__global__ __launch_bounds__(256) void k_first(const float* __restrict__ x,
                                               const float* __restrict__ w1,
                                               const float* __restrict__ b1,
                                               float* __restrict__ out) {
    __shared__ float xs[64][NIN];
    __shared__ float ws[64][NIN + 1];
    const int t0 = blockIdx.x * 64;
    const int h0 = blockIdx.y * 64;
    const int tid = threadIdx.x;

    for (int i = tid; i < 64 * NIN; i += 256)
        xs[i >> 6][i & 63] = x[(size_t)(t0 + (i >> 6)) * NIN + (i & 63)];
    for (int i = tid; i < 64 * NIN; i += 256)
        ws[i >> 6][i & 63] = w1[(size_t)(h0 + (i >> 6)) * NIN + (i & 63)];
    __syncthreads();

    const int h = tid & 63, tq = tid >> 6;
    float acc[16];
#pragma unroll
    for (int i = 0; i < 16; i++) acc[i] = 0.0f;

#pragma unroll 16
    for (int k = 0; k < NIN; k++) {
        const float wv = ws[h][k];
#pragma unroll
        for (int i = 0; i < 16; i++) acc[i] = fmaf(xs[tq * 16 + i][k], wv, acc[i]);
    }
    const float bb = b1[h0 + h];
#pragma unroll
    for (int i = 0; i < 16; i++) {
        float v = acc[i] + bb;
        v = (v >= 0.0f) ? v : 0.01f * v;
        out[(size_t)(t0 + tq * 16 + i) * HD + h0 + h] = v;
    }
}

// ---------------- layer-0 input GEMM: Z0 = X0 @ Wih0^T (biasless) ------------
__global__ __launch_bounds__(256, 2) void k_gemm(const float* __restrict__ A,
                                                 const float* __restrict__ W,
                                                 float* __restrict__ Z) {
    __shared__ float As[8][128];
    __shared__ float Bs[8][128];
    const int tid = threadIdx.x;
    const int tx = tid & 15, ty = tid >> 4;
    const int m0 = blockIdx.y * 128, n0 = blockIdx.x * 128;
    const int lr = tid >> 1, lk = (tid & 1) * 4;

    const float* Ap = A + (size_t)(m0 + lr) * HD + lk;
    const float* Wp = W + (size_t)(n0 + lr) * HD + lk;

    float acc[8][8];
#pragma unroll
    for (int i = 0; i < 8; i++)
#pragma unroll
        for (int j = 0; j < 8; j++) acc[i][j] = 0.0f;

    float4 av = *(const float4*)(Ap);
    float4 bv = *(const float4*)(Wp);

    for (int k0 = 0; k0 < HD; k0 += 8) {
        __syncthreads();
        As[lk + 0][lr] = av.x; As[lk + 1][lr] = av.y; As[lk + 2][lr] = av.z; As[lk + 3][lr] = av.w;
        Bs[lk + 0][lr] = bv.x; Bs[lk + 1][lr] = bv.y; Bs[lk + 2][lr] = bv.z; Bs[lk + 3][lr] = bv.w;
        __syncthreads();
        if (k0 + 8 < HD) {
            av = *(const float4*)(Ap + k0 + 8);
            bv = *(const float4*)(Wp + k0 + 8);
        }
#pragma unroll
        for (int kk = 0; kk < 8; kk++) {
            float ar[8], br[8];
            *(float4*)(ar)     = *(const float4*)&As[kk][ty * 8];
            *(float4*)(ar + 4) = *(const float4*)&As[kk][ty * 8 + 4];
            *(float4*)(br)     = *(const float4*)&Bs[kk][tx * 8];
            *(float4*)(br + 4) = *(const float4*)&Bs[kk][tx * 8 + 4];
#pragma unroll
            for (int i = 0; i < 8; i++)
#pragma unroll
                for (int j = 0; j < 8; j++) acc[i][j] = fmaf(ar[i], br[j], acc[i][j]);
        }
    }
#pragma unroll
    for (int i = 0; i < 8; i++) {
        const size_t m = (size_t)(m0 + ty * 8 + i);
        float4 o0, o1;
        o0.x = acc[i][0]; o0.y = acc[i][1]; o0.z = acc[i][2]; o0.w = acc[i][3];
        o1.x = acc[i][4]; o1.y = acc[i][5]; o1.z = acc[i][6]; o1.w = acc[i][7];
        *(float4*)&Z[m * G4 + n0 + tx * 8]     = o0;
        *(float4*)&Z[m * G4 + n0 + tx * 8 + 4] = o1;
    }
}

// ---------------- fat kernel: rec (CTAs 0..127) + chase gemm (128..275) ------
// rec: R2-proven recurrence. CTA b owns units [8b,8b+8); warp w -> u = 8b+w.
// chase: Z_{l+1} = X_l @ Wih_{l+1}^T, 128x128 tiles grabbed via atomic counter
// in m-major order; each tile waits (flag poll, nanosleep backoff) until rec
// has published its 128 timesteps. Single launch -> graph-capture-safe; kernel
// boundary is the join before rec(l+1).
__global__ __launch_bounds__(256, 1) void k_rec(const float* __restrict__ Whh,  // (G4, HD)
                                                const float* __restrict__ Wn,   // Wih_{l+1}
                                                const float* __restrict__ c0l,
                                                const float* __restrict__ bih,
                                                const float* __restrict__ bhh,
                                                const float* __restrict__ Zin,  // (SEQ, G4) biasless
                                                float* __restrict__ Zout,       // (SEQ, G4) biasless
                                                float* __restrict__ Xio,        // (SEQ, HD) rec out / chase in
                                                unsigned base, int fuse, int layer) {
    __shared__ float smem[2048];
    __shared__ int s_tile;
    const int tid = threadIdx.x;

    if (blockIdx.x < NCTA) {
        // ================= recurrent path =================
        const int w = tid >> 5, lane = tid & 31;
        const int u = blockIdx.x * 8 + w;

        unsigned sb;
        asm("{ .reg .u64 t; cvta.to.shared.u64 t, %1; cvt.u32.u64 %0, t; }"
            : "=r"(sb) : "l"((void*)smem));
        sb += (unsigned)lane * 8u;

        unsigned long long wp[4][16];
#pragma unroll
        for (int g = 0; g < 4; g++) {
            const float* rp = Whh + (size_t)(g * HD + u) * HD + 2 * lane;
#pragma unroll
            for (int j = 0; j < 16; j++) {
                const float2 v = *(const float2*)(rp + 64 * j);
                asm("mov.b64 %0, {%1, %2};" : "=l"(wp[g][j]) : "f"(v.x), "f"(v.y));
            }
        }
        float zb0 = 0.f, zb1 = 0.f, zb2 = 0.f, zb3 = 0.f, c = 0.f;
        if (lane == 0) {
            zb0 = bih[u] + bhh[u];
            zb1 = bih[HD + u] + bhh[HD + u];
            zb2 = bih[2 * HD + u] + bhh[2 * HD + u];
            zb3 = bih[3 * HD + u] + bhh[3 * HD + u];
            c = c0l[u];
        }

#pragma unroll 1
        for (int t = 0; t < SEQ; t++) {
            float z0 = 0.f, z1 = 0.f, z2 = 0.f, z3 = 0.f;
            if (lane == 0) {
                const float* zp = Zin + (size_t)t * G4 + u;
                z0 = __ldcg(zp); z1 = __ldcg(zp + HD);
                z2 = __ldcg(zp + 2 * HD); z3 = __ldcg(zp + 3 * HD);
            }
            const unsigned target = base + (unsigned)t;
            {
                const unsigned* fp = &g_flags[tid >> 1];
                while (ld_acq(fp) < target) {}
                const float4 v = __ldcg((const float4*)(g_h + ((t + 1) & 1) * HD) + tid);
                *(float4*)&smem[(t & 1) * 1024 + tid * 4] = v;
            }
            __syncthreads();

            const unsigned sbase = sb + (unsigned)((t & 1) << 12);
            unsigned long long a0 = 0ull, a1 = 0ull, a2 = 0ull, a3 = 0ull;
#pragma unroll
            for (int j = 0; j < 16; j++) {
                unsigned long long hp;
                asm volatile("ld.shared.b64 %0, [%1];" : "=l"(hp) : "r"(sbase + (unsigned)(j * 256)));
                asm("fma.rn.f32x2 %0, %1, %2, %0;" : "+l"(a0) : "l"(wp[0][j]), "l"(hp));
                asm("fma.rn.f32x2 %0, %1, %2, %0;" : "+l"(a1) : "l"(wp[1][j]), "l"(hp));
                asm("fma.rn.f32x2 %0, %1, %2, %0;" : "+l"(a2) : "l"(wp[2][j]), "l"(hp));
                asm("fma.rn.f32x2 %0, %1, %2, %0;" : "+l"(a3) : "l"(wp[3][j]), "l"(hp));
            }
            float s0, s1, s2, s3;
            {
                float x, y;
                asm("mov.b64 {%0,%1}, %2;" : "=f"(x), "=f"(y) : "l"(a0)); s0 = x + y;
                asm("mov.b64 {%0,%1}, %2;" : "=f"(x), "=f"(y) : "l"(a1)); s1 = x + y;
                asm("mov.b64 {%0,%1}, %2;" : "=f"(x), "=f"(y) : "l"(a2)); s2 = x + y;
                asm("mov.b64 {%0,%1}, %2;" : "=f"(x), "=f"(y) : "l"(a3)); s3 = x + y;
            }
#pragma unroll
            for (int off = 16; off; off >>= 1) {
                s0 += __shfl_xor_sync(0xffffffffu, s0, off);
                s1 += __shfl_xor_sync(0xffffffffu, s1, off);
                s2 += __shfl_xor_sync(0xffffffffu, s2, off);
                s3 += __shfl_xor_sync(0xffffffffu, s3, off);
            }
            if (lane == 0) {
                const float ig = sigmf(s0 + z0 + zb0);
                const float fg = sigmf(s1 + z1 + zb1);
                const float gg = tanh_fast(s2 + z2 + zb2);
                const float og = sigmf(s3 + z3 + zb3);
                c = fg * c + ig * gg;
                const float h = og * tanh_fast(c);
                __stcg(&g_h[(t & 1) * HD + u], h);
                Xio[(size_t)t * HD + u] = h;        // pre-barrier: flag covers it
            }
            __syncthreads();
            if (tid == 0) {
                __threadfence();
                st_relx(&g_flags[blockIdx.x], target + 1u);
            }
        }
    } else {
        // ================= chase GEMM path =================
        if (!fuse) return;
        const int tx = tid & 15, ty = tid >> 4;
        const int lr = tid >> 1, lk = (tid & 1) * 4;
        float* As = smem;            // [8][128]
        float* Bs = smem + 1024;     // [8][128]
        unsigned polled = 0;

        for (;;) {
            if (tid == 0) s_tile = atomicAdd(&g_tilectr[layer], 1);
            __syncthreads();
            const int tile = s_tile;
            if (tile >= CH_TILES) break;
            const int m0 = (tile >> 5) << 7;     // m-major: m advances with counter
            const int n0 = (tile & 31) << 7;
            const unsigned need = base + (unsigned)(m0 + 128);
            if (polled < need) {
                const unsigned* fp = &g_flags[tid & 127];
                while (ld_acq(fp) < need) __nanosleep(1024);
                polled = need;
            }
            __syncthreads();

            const float* Ap = Xio + (size_t)(m0 + lr) * HD + lk;
            const float* Wp = Wn + (size_t)(n0 + lr) * HD + lk;
            float acc[8][8];
#pragma unroll
            for (int i = 0; i < 8; i++)
#pragma unroll
                for (int j = 0; j < 8; j++) acc[i][j] = 0.0f;

            float4 av = *(const float4*)(Ap);
            float4 bv = *(const float4*)(Wp);

            for (int k0 = 0; k0 < HD; k0 += 8) {
                __syncthreads();
                As[(lk + 0) * 128 + lr] = av.x; As[(lk + 1) * 128 + lr] = av.y;
                As[(lk + 2) * 128 + lr] = av.z; As[(lk + 3) * 128 + lr] = av.w;
                Bs[(lk + 0) * 128 + lr] = bv.x; Bs[(lk + 1) * 128 + lr] = bv.y;
                Bs[(lk + 2) * 128 + lr] = bv.z; Bs[(lk + 3) * 128 + lr] = bv.w;
                __syncthreads();
                if (k0 + 8 < HD) {
                    av = *(const float4*)(Ap + k0 + 8);
                    bv = *(const float4*)(Wp + k0 + 8);
                }
#pragma unroll
                for (int kk = 0; kk < 8; kk++) {
                    float ar[8], br[8];
                    *(float4*)(ar)     = *(const float4*)&As[kk * 128 + ty * 8];
                    *(float4*)(ar + 4) = *(const float4*)&As[kk * 128 + ty * 8 + 4];
                    *(float4*)(br)     = *(const float4*)&Bs[kk * 128 + tx * 8];
                    *(float4*)(br + 4) = *(const float4*)&Bs[kk * 128 + tx * 8 + 4];
#pragma unroll
                    for (int i = 0; i < 8; i++)
#pragma unroll
                        for (int j = 0; j < 8; j++) acc[i][j] = fmaf(ar[i], br[j], acc[i][j]);
                }
            }
#pragma unroll
            for (int i = 0; i < 8; i++) {
                const size_t m = (size_t)(m0 + ty * 8 + i);
                float4 o0, o1;
                o0.x = acc[i][0]; o0.y = acc[i][1]; o0.z = acc[i][2]; o0.w = acc[i][3];
                o1.x = acc[i][4]; o1.y = acc[i][5]; o1.z = acc[i][6]; o1.w = acc[i][7];
                *(float4*)&Zout[m * G4 + n0 + tx * 8]     = o0;
                *(float4*)&Zout[m * G4 + n0 + tx * 8 + 4] = o1;
            }
            __syncthreads();   // SMEM safe before next tile
        }
    }
}

// ---------------- final: tanh(leaky_relu(X) @ w2^T + b2) ---------------------
__global__ __launch_bounds__(256) void k_final(const float* __restrict__ Xin,
                                               const float* __restrict__ w2,
                                               const float* __restrict__ b2,
                                               float* __restrict__ y) {
    __shared__ float xs[64][65];
    __shared__ float ws[64][65];
    const int t0 = blockIdx.x * 64;
    const int tid = threadIdx.x;
    const int o = tid & 63, tq = tid >> 6;

    float acc[16];
#pragma unroll
    for (int i = 0; i < 16; i++) acc[i] = 0.0f;

    for (int k0 = 0; k0 < HD; k0 += 64) {
        __syncthreads();
        for (int i = tid; i < 64 * 64; i += 256) {
            const int r = i >> 6, cc = i & 63;
            float v = Xin[(size_t)(t0 + r) * HD + k0 + cc];
            xs[r][cc] = (v >= 0.0f) ? v : 0.01f * v;
            ws[r][cc] = w2[(size_t)r * HD + k0 + cc];
        }
        __syncthreads();
#pragma unroll 16
        for (int k = 0; k < 64; k++) {
            const float wv = ws[o][k];
#pragma unroll
            for (int i = 0; i < 16; i++) acc[i] = fmaf(xs[tq * 16 + i][k], wv, acc[i]);
        }
    }
    const float bb = b2[o];
#pragma unroll
    for (int i = 0; i < 16; i++)
        y[(size_t)(t0 + tq * 16 + i) * NIN + o] = tanh_fast(acc[i] + bb);
}

// ---------------- host launcher (single stream, capture-safe) ----------------
extern "C" void kernel_launch(void* const* d_in, const int* in_sizes, int n_in,
                              void* d_out, int out_size) {
    const float* data_in = (const float*)d_in[0];
    const float* w1      = (const float*)d_in[1];
    const float* b1      = (const float*)d_in[2];
    const float* W_ih    = (const float*)d_in[3];
    const float* W_hh    = (const float*)d_in[4];
    const float* b_ih    = (const float*)d_in[5];
    const float* b_hh    = (const float*)d_in[6];
    const float* w2      = (const float*)d_in[7];
    const float* b2      = (const float*)d_in[8];
    const float* h0      = (const float*)d_in[9];
    const float* c0      = (const float*)d_in[10];
    float* out = (float*)d_out;

    static float* dA = nullptr;
    static float* dB = nullptr;
    static float* dZ0 = nullptr;
    static float* dZ1 = nullptr;
    if (!dA) {   // host-side symbol queries; not allocations
        cudaGetSymbolAddress((void**)&dA, g_bufA);
        cudaGetSymbolAddress((void**)&dB, g_bufB);
        cudaGetSymbolAddress((void**)&dZ0, g_Z0);
        cudaGetSymbolAddress((void**)&dZ1, g_Z1);
    }
    float* bufs[2] = { dA, dB };
    float* zbuf[2] = { dZ0, dZ1 };

    k_init<<<4, 256>>>(h0);
    k_first<<<dim3(SEQ / 64, HD / 64), 256>>>(data_in, w1, b1, dA);
    k_gemm<<<dim3(G4 / 128, SEQ / 128), 256>>>(dA, W_ih, dZ0);   // layer-0 Z (biasless)

    for (int l = 0; l < NLAYER; l++) {
        float* Xl = bufs[(l + 1) & 1];   // rec(l) output sequence
        const int fuse = (l < NLAYER - 1) ? 1 : 0;
        if (l > 0)
            k_prep<<<4, 256>>>(h0 + (size_t)l * HD);
        k_rec<<<GRID_REC, 256>>>(W_hh + (size_t)l * G4 * HD,
                                 W_ih + (size_t)(fuse ? (l + 1) : l) * G4 * HD,
                                 c0 + (size_t)l * HD,
                                 b_ih + (size_t)l * G4,
                                 b_hh + (size_t)l * G4,
                                 zbuf[l & 1], zbuf[(l + 1) & 1],
                                 Xl,
                                 (unsigned)(l * SEQ), fuse, l);
    }
    k_final<<<SEQ / 64, 256>>>(dB, w2, b2, out);
}